// round 13
// baseline (speedup 1.0000x reference)
#include <cuda_runtime.h>
#include <cuda_fp16.h>
#include <cstdint>

#define VOCAB  16000
#define EMBED  256
#define HIDDEN 512
#define BATCH  8
#define SEQ    2048
#define M_TOK  (BATCH * SEQ)   // 16384

// RNN outputs in fp16 (A of logits GEMM)
__device__ __half g_bufh[(size_t)M_TOK * HIDDEN];
// W_out in fp16 (B of logits GEMM)
__device__ __half g_wth[(size_t)VOCAB * HIDDEN];
// token dtype flag
__device__ int g_is64;
// per-batch RNN progress: 8 CTA-arrivals per completed timestep
__device__ int g_prog[BATCH];

#define CP_A16(dst, src) \
    asm volatile("cp.async.cg.shared.global [%0], [%1], 16;" :: "r"(dst), "l"(src) : "memory")
#define CP_A16Z(dst, src, sz) \
    asm volatile("cp.async.cg.shared.global [%0], [%1], 16, %2;" :: "r"(dst), "l"(src), "r"(sz) : "memory")
#define CP_COMMIT() asm volatile("cp.async.commit_group;" ::: "memory")
#define CP_WAIT(n)  asm volatile("cp.async.wait_group %0;" :: "n"(n) : "memory")

// ---------------------------------------------------------------------------
// Kernel 0: token dtype detection + progress-counter reset (every replay)
// ---------------------------------------------------------------------------
__global__ void detect_kernel(const int* __restrict__ x32) {
    int ok = 1;
    for (int i = 0; i < 128; i++)
        if (x32[2 * i + 1] != 0) ok = 0;
    g_is64 = ok;
    for (int i = 0; i < BATCH; i++) g_prog[i] = 0;
}

// ---------------------------------------------------------------------------
// Kernel 0b: W_out fp32 -> fp16 (RN) into g_wth. Runs as PDL secondary of the
// RNN: overlapped with the RNN's first ~100us on the free SMs.
// ---------------------------------------------------------------------------
__global__ __launch_bounds__(256) void wconv_kernel(const float* __restrict__ w) {
    int t = blockIdx.x * 256 + threadIdx.x;       // 0..511999
    const float4* src = (const float4*)w;
    uint2* dst = (uint2*)g_wth;
    #pragma unroll
    for (int i = 0; i < 4; i++) {
        int idx = t + i * 512000;
        float4 v = src[idx];
        __half2 h0 = __float22half2_rn(make_float2(v.x, v.y));
        __half2 h1 = __float22half2_rn(make_float2(v.z, v.w));
        uint2 o;
        o.x = *(uint32_t*)&h0;
        o.y = *(uint32_t*)&h1;
        dst[idx] = o;
    }
}

// ---------------------------------------------------------------------------
// Kernel 2: sequential RNN scan with FUSED x-projection.
// R6-proven barrier structure (8-CTA cluster, 256 thr, one barrier.cluster
// per step, single h-FMA chain, q==0 post+fanout). Additions:
//  * W_ih slice (64 rows x 256) in SMEM, padded [64][4][68] (row stride 272,
//    quarter stride 68 -> conflict-free LDS for (r,q) fragment reads).
//  * x_proj[b,t+1] computed in the barrier shadow (64-FMA chain + butterfly),
//    using an embedding row staged 2 steps ahead by cp.async into a 3-slot
//    ring (mod-3 depth makes writer/reader ordering provable through the
//    cluster-barrier chain).
//  * griddepcontrol.launch_dependents after setup (PDL primary for wconv+GEMM)
//  * per-step release-increment of g_prog[b] (consumed by the GEMM).
// Recurrence exact fp32; output sequence stored fp16-RN.
// ---------------------------------------------------------------------------
// dynamic SMEM layout (float offsets):
//   hbuf   [2][528]      @ 0       (4224 B)
//   es     [3][256]      @ 1056    (3072 B)
//   toks   int[2048]     @ 1824    (8192 B)
//   wih    [64][272]     @ 3872    (69632 B)
#define RNN_SMEM 85120

extern __shared__ char dsmem[];

__global__ void __launch_bounds__(256, 1) __cluster_dims__(8, 1, 1)
rnn_kernel(const long long* __restrict__ x64,
           const int*       __restrict__ x32,
           const float* __restrict__ emb,
           const float* __restrict__ W_ih,
           const float* __restrict__ b_ih,
           const float* __restrict__ hidden,
           const float* __restrict__ W_hh,
           const float* __restrict__ b_hh,
           float* __restrict__ out,
           int hf_off)
{
    float* smemf = (float*)dsmem;
    float* hbuf = smemf;                 // [2][528]
    float* es   = smemf + 1056;          // [3][256]
    int*   toks = (int*)(smemf + 1824);  // [2048]
    float* wih  = smemf + 3872;          // [64][272]

    const int tid = threadIdx.x;
    unsigned c;
    asm("mov.u32 %0, %%cluster_ctarank;" : "=r"(c));
    const int b = blockIdx.y;

    const int q = tid & 3;          // K quarter
    const int r = tid >> 2;         // local row 0..63
    const int row = (int)c * 64 + r;

    // W_hh slice into registers
    float4 w4[32];
    const float4* wp = (const float4*)(W_hh + (long)row * HIDDEN + q * 128);
    #pragma unroll
    for (int i = 0; i < 32; i++) w4[i] = wp[i];

    // tokens for this batch into SMEM
    for (int i = tid; i < SEQ; i += 256)
        toks[i] = g_is64 ? (int)x64[(size_t)b * SEQ + i] : x32[b * SEQ + i];

    // W_ih slice rows [c*64, c*64+64) into padded SMEM
    for (int idx = tid; idx < 64 * 64; idx += 256) {
        int rr = idx >> 6, jj = idx & 63;          // row, 4-col chunk
        float4 v = *(const float4*)(W_ih + (size_t)((int)c * 64 + rr) * EMBED + jj * 4);
        *(float4*)(wih + rr * 272 + (jj >> 4) * 68 + (jj & 15) * 4) = v;
    }

    // h buffer 0
    for (int i = tid; i < HIDDEN; i += 256)
        hbuf[(i >> 7) * 132 + (i & 127)] = hidden[b * HIDDEN + i];

    const float bhh_r = (q == 0) ? b_hh[row] : 0.f;
    const float bih_r = b_ih[row];

    uint32_t sbase;
    {
        void* p = (void*)dsmem;
        asm("{ .reg .u64 t; cvta.to.shared.u64 t, %1; cvt.u32.u64 %0, t; }"
            : "=r"(sbase) : "l"(p));
    }
    const int pp = (row >> 7) * 132 + (row & 127);
    const uint32_t slot0 = sbase + (uint32_t)pp * 4u;
    const uint32_t slot1 = sbase + (uint32_t)(528 + pp) * 4u;
    const uint32_t esb   = sbase + 1056u * 4u;     // es byte base; slot stride 1024

    const size_t xpi = (size_t)b * SEQ * HIDDEN + row;

    __syncthreads();   // smem setup complete

    // release PDL dependents (wconv, then GEMM)
    asm volatile("griddepcontrol.launch_dependents;" ::: "memory");

    // prologue: stage emb rows for t=0 (slot 0) and t=1 (slot 1)
    if (tid < 64) {
        int tok0 = toks[0];
        int tok1 = toks[1];
        CP_A16(esb + tid * 16u,          emb + (size_t)tok0 * EMBED + tid * 4);
        CP_A16(esb + 1024u + tid * 16u,  emb + (size_t)tok1 * EMBED + tid * 4);
    }
    CP_COMMIT();
    CP_WAIT(0);
    __syncthreads();

    const float* wr = wih + r * 272 + q * 68;

    // xp for t=0 from slot 0
    float xv;
    {
        const float* e0 = es + q * 64;
        float xa = 0.f;
        #pragma unroll
        for (int i = 0; i < 16; i++) {
            float4 w = *(const float4*)(wr + 4 * i);
            float4 e = *(const float4*)(e0 + 4 * i);
            xa = fmaf(w.x, e.x, xa);
            xa = fmaf(w.y, e.y, xa);
            xa = fmaf(w.z, e.z, xa);
            xa = fmaf(w.w, e.w, xa);
        }
        xa += __shfl_xor_sync(0xffffffffu, xa, 1);
        xa += __shfl_xor_sync(0xffffffffu, xa, 2);
        xv = xa + bih_r;
    }

    int* progp = &g_prog[b];

    #pragma unroll 1
    for (int t = 0; t < SEQ; t++) {
        // h chain (proven R6 form)
        const float* hs = &hbuf[(t & 1) * 528 + q * 132];
        float acc = 0.f;
        #pragma unroll
        for (int i = 0; i < 32; i++) {
            float4 h4 = *(const float4*)(hs + 4 * i);
            acc = fmaf(w4[i].x, h4.x, acc);
            acc = fmaf(w4[i].y, h4.y, acc);
            acc = fmaf(w4[i].z, h4.z, acc);
            acc = fmaf(w4[i].w, h4.w, acc);
        }
        acc += __shfl_xor_sync(0xffffffffu, acc, 1);
        acc += __shfl_xor_sync(0xffffffffu, acc, 2);

        if (q == 0) {
            float v = tanhf(acc + xv + bhh_r);
            g_bufh[xpi + (size_t)t * HIDDEN] = __float2half_rn(v);
            if (t == SEQ - 1)
                out[hf_off + b * HIDDEN + row] = v;   // exact fp32 h_final
            const uint32_t dstoff = ((t + 1) & 1) ? slot1 : slot0;
            uint32_t vbits = __float_as_uint(v);
            #pragma unroll
            for (int dst = 0; dst < 8; dst++) {
                asm volatile(
                    "{ .reg .b32 ra;\n\t"
                    "  mapa.shared::cluster.u32 ra, %0, %1;\n\t"
                    "  st.shared::cluster.b32 [ra], %2; }"
                    :: "r"(dstoff), "r"(dst), "r"(vbits) : "memory");
            }
        }
        asm volatile("barrier.cluster.arrive.aligned;" ::: "memory");

        // ------- barrier shadow -------
        // stage emb row for t+2 into slot (t+2)%3
        {
            int t2 = t + 2;
            if (tid < 64 && t2 < SEQ) {
                int tk = toks[t2];
                uint32_t sl = (uint32_t)(t2 % 3);
                CP_A16(esb + sl * 1024u + tid * 16u,
                       emb + (size_t)tk * EMBED + tid * 4);
            }
        }
        CP_COMMIT();
        CP_WAIT(1);        // group from step t-1 (emb row t+1) complete
        __syncthreads();   // cp.async writes visible CTA-wide

        // xp for t+1 from slot (t+1)%3
        float xvn = 0.f;
        if (t + 1 < SEQ) {
            const float* e0 = es + ((t + 1) % 3) * 256 + q * 64;
            float xa = 0.f;
            #pragma unroll
            for (int i = 0; i < 16; i++) {
                float4 w = *(const float4*)(wr + 4 * i);
                float4 e = *(const float4*)(e0 + 4 * i);
                xa = fmaf(w.x, e.x, xa);
                xa = fmaf(w.y, e.y, xa);
                xa = fmaf(w.z, e.z, xa);
                xa = fmaf(w.w, e.w, xa);
            }
            xa += __shfl_xor_sync(0xffffffffu, xa, 1);
            xa += __shfl_xor_sync(0xffffffffu, xa, 2);
            xvn = xa + bih_r;
        }
        // ------- end shadow -------

        asm volatile("barrier.cluster.wait.aligned;" ::: "memory");

        // publish step-t completion to the concurrently-running GEMM
        if (tid == 0)
            asm volatile("red.release.gpu.global.add.s32 [%0], 1;"
                         :: "l"(progp) : "memory");
        xv = xvn;
    }
}

// ---------------------------------------------------------------------------
// Kernel 3: logits GEMM via warp-level mma.sync fp16 (m16n8k16, fp32 accum).
// PDL secondary (starts after wconv completes, while the RNN runs). Tile
// order t-major; each CTA spin-waits on g_prog[batch] for its 128 timesteps.
// Tile 128x256, 8 warps, K-stage 64 halves, 3-buffer cp.async pipeline.
// Grid (63, 128), 256 threads, dyn smem 165888 B.
// ---------------------------------------------------------------------------
#define LG_STRIDE 72                          // halves per SMEM row
#define LGA_BYTES (128 * LG_STRIDE * 2)       // 18432
#define LGB_BYTES (256 * LG_STRIDE * 2)       // 36864
#define LG_STAGE  (LGA_BYTES + LGB_BYTES)     // 55296
#define LG_SMEM   (3 * LG_STAGE)              // 165888

__global__ __launch_bounds__(256) void logits_mma_kernel(
    const float* __restrict__ b_out,
    float* __restrict__ out)
{
    const uint32_t sb = (uint32_t)__cvta_generic_to_shared(dsmem);

    const int tid  = threadIdx.x;
    const int wid  = tid >> 5;
    const int lane = tid & 31;
    const int gr   = lane >> 2;     // 0..7
    const int gc   = lane & 3;      // 0..3
    const int wm   = wid & 1;       // warp m index
    const int wn   = wid >> 1;      // warp n index

    const int n0 = blockIdx.x * 256;
    // t-major tile order: earliest timesteps first in block-linear order
    const int batch = blockIdx.y & 7;
    const int tch   = blockIdx.y >> 3;        // 0..15
    const int m0 = batch * SEQ + tch * 128;

    // per-thread cp.async assignments (16B = 8 halves per chunk)
    uint32_t aDst[4]; const char* aSrc[4];
    #pragma unroll
    for (int i = 0; i < 4; i++) {
        int ch = tid + i * 256;               // 0..1023
        int row = ch >> 3, qq = ch & 7;
        aDst[i] = (uint32_t)(row * (LG_STRIDE * 2) + qq * 16);
        aSrc[i] = (const char*)(g_bufh + (size_t)(m0 + row) * HIDDEN + qq * 8);
    }
    uint32_t bDst[8]; const char* bSrc[8]; uint32_t bSz[8];
    #pragma unroll
    for (int i = 0; i < 8; i++) {
        int ch = tid + i * 256;               // 0..2047
        int row = ch >> 3, qq = ch & 7;
        bDst[i] = (uint32_t)(LGA_BYTES + row * (LG_STRIDE * 2) + qq * 16);
        int n = n0 + row;
        bSz[i] = (n < VOCAB) ? 16u : 0u;
        if (n >= VOCAB) n = VOCAB - 1;
        bSrc[i] = (const char*)(g_wth + (size_t)n * HIDDEN + qq * 8);
    }

    // wait until the RNN has published all 128 timesteps of this tile
    {
        const int target = 8 * (tch * 128 + 128);
        if (tid == 0) {
            const int* pp = &g_prog[batch];
            int p;
            while (true) {
                asm volatile("ld.acquire.gpu.global.b32 %0, [%1];"
                             : "=r"(p) : "l"(pp) : "memory");
                if (p >= target) break;
                __nanosleep(256);
            }
        }
        __syncthreads();
    }

    float c[4][8][4];
    #pragma unroll
    for (int mi = 0; mi < 4; mi++)
        #pragma unroll
        for (int ni = 0; ni < 8; ni++)
            #pragma unroll
            for (int j = 0; j < 4; j++) c[mi][ni][j] = 0.f;

    // prologue: stages 0 and 1 (each stage advances 64 halves = 128 bytes)
    #pragma unroll
    for (int st = 0; st < 2; st++) {
        uint32_t base = sb + st * LG_STAGE;
        #pragma unroll
        for (int i = 0; i < 4; i++) CP_A16(base + aDst[i], aSrc[i] + st * 128);
        #pragma unroll
        for (int i = 0; i < 8; i++) CP_A16Z(base + bDst[i], bSrc[i] + st * 128, bSz[i]);
        CP_COMMIT();
    }

    const int aOffBase = (wm * 64 + gr) * LG_STRIDE + 2 * gc;
    const int bOffBase = (wn * 64 + gr) * LG_STRIDE + 2 * gc;

    #pragma unroll 1
    for (int ks = 0; ks < 8; ks++) {
        if (ks < 7) CP_WAIT(1); else CP_WAIT(0);
        __syncthreads();

        if (ks + 2 < 8) {
            const int st = ks + 2;
            uint32_t base = sb + (uint32_t)(st % 3) * LG_STAGE;
            #pragma unroll
            for (int i = 0; i < 4; i++) CP_A16(base + aDst[i], aSrc[i] + st * 128);
            #pragma unroll
            for (int i = 0; i < 8; i++) CP_A16Z(base + bDst[i], bSrc[i] + st * 128, bSz[i]);
            CP_COMMIT();
        }

        const __half* bufA = (const __half*)(dsmem + (ks % 3) * LG_STAGE);
        const __half* bufB = bufA + LGA_BYTES / 2;

        #pragma unroll
        for (int kk = 0; kk < 64; kk += 16) {
            uint32_t a[4][4];
            #pragma unroll
            for (int mi = 0; mi < 4; mi++) {
                const __half* p = bufA + aOffBase + mi * 16 * LG_STRIDE + kk;
                a[mi][0] = *(const uint32_t*)(p);
                a[mi][1] = *(const uint32_t*)(p + 8 * LG_STRIDE);
                a[mi][2] = *(const uint32_t*)(p + 8);
                a[mi][3] = *(const uint32_t*)(p + 8 * LG_STRIDE + 8);
            }
            uint32_t bfr[8][2];
            #pragma unroll
            for (int ni = 0; ni < 8; ni++) {
                const __half* p = bufB + bOffBase + ni * 8 * LG_STRIDE + kk;
                bfr[ni][0] = *(const uint32_t*)(p);
                bfr[ni][1] = *(const uint32_t*)(p + 8);
            }
            #pragma unroll
            for (int mi = 0; mi < 4; mi++)
                #pragma unroll
                for (int ni = 0; ni < 8; ni++) {
                    asm volatile(
                        "mma.sync.aligned.m16n8k16.row.col.f32.f16.f16.f32 "
                        "{%0,%1,%2,%3}, {%4,%5,%6,%7}, {%8,%9}, {%0,%1,%2,%3};"
                        : "+f"(c[mi][ni][0]), "+f"(c[mi][ni][1]),
                          "+f"(c[mi][ni][2]), "+f"(c[mi][ni][3])
                        : "r"(a[mi][0]), "r"(a[mi][1]), "r"(a[mi][2]), "r"(a[mi][3]),
                          "r"(bfr[ni][0]), "r"(bfr[ni][1]));
                }
        }
    }

    // epilogue: direct gmem stores + bias
    const int mBase = m0 + wm * 64 + gr;
    const int nBase = n0 + wn * 64 + gc * 2;
    #pragma unroll
    for (int ni = 0; ni < 8; ni++) {
        int col = nBase + ni * 8;
        if (col < VOCAB) {
            float2 bias = *(const float2*)(b_out + col);
            #pragma unroll
            for (int mi = 0; mi < 4; mi++) {
                int r0 = mBase + mi * 16;
                float2 v0 = make_float2(c[mi][ni][0] + bias.x, c[mi][ni][1] + bias.y);
                float2 v1 = make_float2(c[mi][ni][2] + bias.x, c[mi][ni][3] + bias.y);
                *(float2*)(out + (size_t)r0 * VOCAB + col)       = v0;
                *(float2*)(out + (size_t)(r0 + 8) * VOCAB + col) = v1;
            }
        }
    }
}

// ---------------------------------------------------------------------------
// Inputs (metadata order):
//  0:x [8,2048] i64/i32  1:hidden [8,512]  2:embedding [16000,256]
//  3:W_ih [512,256]  4:W_hh [512,512]  5:b_ih [512]  6:b_hh [512]
//  7:W_out [16000,512]  8:b_out [16000]
// Output: logits [8,2048,16000] f32 then h_final [8,512] f32.
// ---------------------------------------------------------------------------
extern "C" void kernel_launch(void* const* d_in, const int* in_sizes, int n_in,
                              void* d_out, int out_size)
{
    const long long* x64   = (const long long*)d_in[0];
    const int*       x32   = (const int*)d_in[0];
    const float* hidden    = (const float*)d_in[1];
    const float* embedding = (const float*)d_in[2];
    const float* W_ih      = (const float*)d_in[3];
    const float* W_hh      = (const float*)d_in[4];
    const float* b_ih      = (const float*)d_in[5];
    const float* b_hh      = (const float*)d_in[6];
    const float* W_out     = (const float*)d_in[7];
    const float* b_out     = (const float*)d_in[8];
    float* out = (float*)d_out;

    const int hf_off = out_size - BATCH * HIDDEN;

    static bool attr_set = false;
    if (!attr_set) {
        cudaFuncSetAttribute(logits_mma_kernel,
                             cudaFuncAttributeMaxDynamicSharedMemorySize, LG_SMEM);
        cudaFuncSetAttribute(rnn_kernel,
                             cudaFuncAttributeMaxDynamicSharedMemorySize, RNN_SMEM);
        attr_set = true;
    }

    detect_kernel<<<1, 1>>>(x32);

    // RNN: PDL primary (fires launch_dependents ~10us in)
    rnn_kernel<<<dim3(8, 8), 256, RNN_SMEM>>>(
        x64, x32, embedding, W_ih, b_ih, hidden, W_hh, b_hh, out, hf_off);

    // wconv: PDL secondary of the RNN — runs on free SMs during RNN start
    {
        cudaLaunchConfig_t cfg = {};
        cfg.gridDim  = dim3(2000);
        cfg.blockDim = dim3(256);
        cfg.dynamicSmemBytes = 0;
        cfg.stream = 0;
        cudaLaunchAttribute attrs[1];
        attrs[0].id = cudaLaunchAttributeProgrammaticStreamSerialization;
        attrs[0].val.programmaticStreamSerializationAllowed = 1;
        cfg.attrs = attrs;
        cfg.numAttrs = 1;
        cudaLaunchKernelEx(&cfg, wconv_kernel, W_out);
    }

    // logits GEMM: PSS w.r.t. wconv (no launch_dependents in wconv -> starts
    // at wconv completion, guaranteeing g_wth is fully written), overlapped
    // with the still-running RNN via g_prog spin-waits.
    {
        cudaLaunchConfig_t cfg = {};
        cfg.gridDim  = dim3(63, 128);
        cfg.blockDim = dim3(256);
        cfg.dynamicSmemBytes = LG_SMEM;
        cfg.stream = 0;
        cudaLaunchAttribute attrs[1];
        attrs[0].id = cudaLaunchAttributeProgrammaticStreamSerialization;
        attrs[0].val.programmaticStreamSerializationAllowed = 1;
        cfg.attrs = attrs;
        cfg.numAttrs = 1;
        cudaLaunchKernelEx(&cfg, logits_mma_kernel, b_out, out);
    }
}

// round 14
// speedup vs baseline: 2.8743x; 2.8743x over previous
#include <cuda_runtime.h>
#include <cuda_fp16.h>
#include <cstdint>

#define VOCAB  16000
#define EMBED  256
#define HIDDEN 512
#define BATCH  8
#define SEQ    2048
#define M_TOK  (BATCH * SEQ)   // 16384

// fp32 x_proj (exact input to the recurrence)
__device__ float g_buf[(size_t)M_TOK * HIDDEN];
// RNN outputs in fp16 (A of logits GEMM)
__device__ __half g_bufh[(size_t)M_TOK * HIDDEN];
// W_out in fp16 (B of logits GEMM)
__device__ __half g_wth[(size_t)VOCAB * HIDDEN];
// token dtype flag
__device__ int g_is64;
// per-batch RNN progress: 8 CTA-arrivals per completed timestep
__device__ int g_prog[BATCH];

#define CP_A16(dst, src) \
    asm volatile("cp.async.cg.shared.global [%0], [%1], 16;" :: "r"(dst), "l"(src) : "memory")
#define CP_A16Z(dst, src, sz) \
    asm volatile("cp.async.cg.shared.global [%0], [%1], 16, %2;" :: "r"(dst), "l"(src), "r"(sz) : "memory")
#define CP_COMMIT() asm volatile("cp.async.commit_group;" ::: "memory")
#define CP_WAIT(n)  asm volatile("cp.async.wait_group %0;" :: "n"(n) : "memory")

// ---------------------------------------------------------------------------
// Kernel 0: token dtype detection + progress-counter reset (every replay)
// ---------------------------------------------------------------------------
__global__ void detect_kernel(const int* __restrict__ x32) {
    int ok = 1;
    for (int i = 0; i < 128; i++)
        if (x32[2 * i + 1] != 0) ok = 0;
    g_is64 = ok;
    for (int i = 0; i < BATCH; i++) g_prog[i] = 0;
}

// ---------------------------------------------------------------------------
// Kernel 1: combined prep — one grid overlapping two independent jobs:
//   blocks [0, 2000):    W_out fp32 -> fp16 (RN) into g_wth (DRAM-bound)
//   blocks [2000, 2512): x_proj = gather(emb, x) @ W_ih^T + b_ih (FMA-bound)
// ---------------------------------------------------------------------------
__global__ __launch_bounds__(256, 2) void prep_kernel(
    const float*     __restrict__ w_out,
    const long long* __restrict__ x64,
    const int*       __restrict__ x32,
    const float*     __restrict__ emb,
    const float*     __restrict__ W_ih,
    const float*     __restrict__ b_ih)
{
    const int bid = blockIdx.x;
    const int tid = threadIdx.x;

    if (bid < 2000) {
        // ---- wconv part ----
        int t = bid * 256 + tid;                  // 0..511999
        const float4* src = (const float4*)w_out;
        uint2* dst = (uint2*)g_wth;
        #pragma unroll
        for (int i = 0; i < 4; i++) {
            int idx = t + i * 512000;
            float4 v = src[idx];
            __half2 h0 = __float22half2_rn(make_float2(v.x, v.y));
            __half2 h1 = __float22half2_rn(make_float2(v.z, v.w));
            uint2 o;
            o.x = *(uint32_t*)&h0;
            o.y = *(uint32_t*)&h1;
            dst[idx] = o;
        }
        return;
    }

    // ---- xproj part ----
    __shared__ float As[8][132];
    __shared__ float Bs[8][132];
    __shared__ int   xid[128];

    const int idx = bid - 2000;                   // 0..511
    const int n0 = (idx & 3) * 128;
    const int m0 = (idx >> 2) * 128;

    if (tid < 128) {
        int m = m0 + tid;
        xid[tid] = g_is64 ? (int)x64[m] : x32[m];
    }
    __syncthreads();

    const int tx = tid & 15, ty = tid >> 4;
    const int lrow = tid >> 1;
    const int lq   = (tid & 1) * 4;

    const long  aBase = (long)xid[lrow] * EMBED + lq;
    const float* bRow = W_ih + (long)(n0 + lrow) * EMBED + lq;

    float acc[8][8];
    #pragma unroll
    for (int i = 0; i < 8; i++)
        #pragma unroll
        for (int j = 0; j < 8; j++) acc[i][j] = 0.f;

    for (int k0 = 0; k0 < EMBED; k0 += 8) {
        float4 av = *(const float4*)(emb + aBase + k0);
        float4 bv = *(const float4*)(bRow + k0);
        __syncthreads();
        As[lq + 0][lrow] = av.x; As[lq + 1][lrow] = av.y;
        As[lq + 2][lrow] = av.z; As[lq + 3][lrow] = av.w;
        Bs[lq + 0][lrow] = bv.x; Bs[lq + 1][lrow] = bv.y;
        Bs[lq + 2][lrow] = bv.z; Bs[lq + 3][lrow] = bv.w;
        __syncthreads();
        #pragma unroll
        for (int kk = 0; kk < 8; kk++) {
            float a[8], bb[8];
            #pragma unroll
            for (int i = 0; i < 8; i++) a[i] = As[kk][ty * 8 + i];
            #pragma unroll
            for (int j = 0; j < 8; j++) bb[j] = Bs[kk][tx * 8 + j];
            #pragma unroll
            for (int i = 0; i < 8; i++)
                #pragma unroll
                for (int j = 0; j < 8; j++)
                    acc[i][j] = fmaf(a[i], bb[j], acc[i][j]);
        }
    }

    float bias[8];
    #pragma unroll
    for (int j = 0; j < 8; j++) bias[j] = b_ih[n0 + tx * 8 + j];

    #pragma unroll
    for (int i = 0; i < 8; i++) {
        size_t o = (size_t)(m0 + ty * 8 + i) * HIDDEN + n0 + tx * 8;
        float4 v0 = make_float4(acc[i][0] + bias[0], acc[i][1] + bias[1],
                                acc[i][2] + bias[2], acc[i][3] + bias[3]);
        float4 v1 = make_float4(acc[i][4] + bias[4], acc[i][5] + bias[5],
                                acc[i][6] + bias[6], acc[i][7] + bias[7]);
        *(float4*)(g_buf + o)     = v0;
        *(float4*)(g_buf + o + 4) = v1;
    }
}

// ---------------------------------------------------------------------------
// Kernel 2: sequential RNN scan — R6/R10-proven structure (cluster.sync per
// step, single FMA chain, q==0 post+fanout), PDL primary + per-step
// release-increment of g_prog[b] consumed by the overlapped GEMM.
// ---------------------------------------------------------------------------
__global__ void __launch_bounds__(256, 1) __cluster_dims__(8, 1, 1)
rnn_kernel(const float* __restrict__ hidden,
           const float* __restrict__ W_hh,
           const float* __restrict__ b_hh,
           float* __restrict__ out,
           int hf_off)
{
    __shared__ float hbuf[2][4 * 132];

    const int tid = threadIdx.x;
    unsigned c;
    asm("mov.u32 %0, %%cluster_ctarank;" : "=r"(c));
    const int b = blockIdx.y;

    const int q = tid & 3;          // K quarter
    const int r = tid >> 2;         // local row 0..63
    const int row = (int)c * 64 + r;

    float4 w4[32];
    const float4* wp = (const float4*)(W_hh + (long)row * HIDDEN + q * 128);
    #pragma unroll
    for (int i = 0; i < 32; i++) w4[i] = wp[i];

    for (int i = tid; i < HIDDEN; i += 256)
        hbuf[0][(i >> 7) * 132 + (i & 127)] = hidden[b * HIDDEN + i];

    const float bhh_r = (q == 0) ? b_hh[row] : 0.f;

    uint32_t sbase;
    {
        void* p = (void*)hbuf;
        asm("{ .reg .u64 t; cvta.to.shared.u64 t, %1; cvt.u32.u64 %0, t; }"
            : "=r"(sbase) : "l"(p));
    }
    const int pp = (row >> 7) * 132 + (row & 127);
    const uint32_t slot0 = sbase + (uint32_t)pp * 4u;
    const uint32_t slot1 = sbase + (uint32_t)(528 + pp) * 4u;

    const size_t xpi = (size_t)b * SEQ * HIDDEN + row;
    float xv = (q == 0) ? g_buf[xpi] : 0.f;

    __syncthreads();

    // allow the logits GEMM (secondary) to begin launching
    asm volatile("griddepcontrol.launch_dependents;" ::: "memory");

    int* progp = &g_prog[b];

    #pragma unroll 1
    for (int t = 0; t < SEQ; t++) {
        float xv_next = 0.f;
        if (q == 0 && t + 1 < SEQ)
            xv_next = g_buf[xpi + (size_t)(t + 1) * HIDDEN];

        const float* hs = &hbuf[t & 1][q * 132];
        float acc = 0.f;
        #pragma unroll
        for (int i = 0; i < 32; i++) {
            float4 h4 = *(const float4*)(hs + 4 * i);
            acc = fmaf(w4[i].x, h4.x, acc);
            acc = fmaf(w4[i].y, h4.y, acc);
            acc = fmaf(w4[i].z, h4.z, acc);
            acc = fmaf(w4[i].w, h4.w, acc);
        }
        acc += __shfl_xor_sync(0xffffffffu, acc, 1);
        acc += __shfl_xor_sync(0xffffffffu, acc, 2);

        if (q == 0) {
            float v = tanhf(acc + xv + bhh_r);
            g_bufh[xpi + (size_t)t * HIDDEN] = __float2half_rn(v);
            if (t == SEQ - 1)
                out[hf_off + b * HIDDEN + row] = v;   // exact fp32 h_final
            const uint32_t dstoff = ((t + 1) & 1) ? slot1 : slot0;
            uint32_t vbits = __float_as_uint(v);
            #pragma unroll
            for (int dst = 0; dst < 8; dst++) {
                asm volatile(
                    "{ .reg .b32 ra;\n\t"
                    "  mapa.shared::cluster.u32 ra, %0, %1;\n\t"
                    "  st.shared::cluster.b32 [ra], %2; }"
                    :: "r"(dstoff), "r"(dst), "r"(vbits) : "memory");
            }
        }
        asm volatile("barrier.cluster.arrive.aligned;" ::: "memory");
        asm volatile("barrier.cluster.wait.aligned;"   ::: "memory");

        // publish step-t completion (stores happened-before the barrier;
        // the barrier happens-before this release-red)
        if (tid == 0)
            asm volatile("red.release.gpu.global.add.s32 [%0], 1;"
                         :: "l"(progp) : "memory");
        xv = xv_next;
    }
}

// ---------------------------------------------------------------------------
// Kernel 3: logits GEMM via warp-level mma.sync fp16 (m16n8k16, fp32 accum).
// PDL secondary of rnn_kernel: starts while the RNN runs. Tile order t-major
// (y -> batch=y&7, t0=(y>>3)*128); each CTA spin-waits on g_prog[batch].
// Tile 128x256, 8 warps, K-stage 64 halves, 3-buffer cp.async pipeline.
// Grid (63, 128), 256 threads, dyn smem 165888 B.
// ---------------------------------------------------------------------------
#define LG_STRIDE 72                          // halves per SMEM row
#define LGA_BYTES (128 * LG_STRIDE * 2)       // 18432
#define LGB_BYTES (256 * LG_STRIDE * 2)       // 36864
#define LG_STAGE  (LGA_BYTES + LGB_BYTES)     // 55296
#define LG_SMEM   (3 * LG_STAGE)              // 165888

__global__ __launch_bounds__(256) void logits_mma_kernel(
    const float* __restrict__ b_out,
    float* __restrict__ out)
{
    extern __shared__ char smem[];
    const uint32_t sb = (uint32_t)__cvta_generic_to_shared(smem);

    const int tid  = threadIdx.x;
    const int wid  = tid >> 5;
    const int lane = tid & 31;
    const int gr   = lane >> 2;     // 0..7
    const int gc   = lane & 3;      // 0..3
    const int wm   = wid & 1;       // warp m index
    const int wn   = wid >> 1;      // warp n index

    const int n0 = blockIdx.x * 256;
    // t-major tile order: earliest timesteps first in block-linear order
    const int batch = blockIdx.y & 7;
    const int tch   = blockIdx.y >> 3;        // 0..15
    const int m0 = batch * SEQ + tch * 128;

    // per-thread cp.async assignments (16B = 8 halves per chunk)
    uint32_t aDst[4]; const char* aSrc[4];
    #pragma unroll
    for (int i = 0; i < 4; i++) {
        int ch = tid + i * 256;               // 0..1023
        int row = ch >> 3, qq = ch & 7;
        aDst[i] = (uint32_t)(row * (LG_STRIDE * 2) + qq * 16);
        aSrc[i] = (const char*)(g_bufh + (size_t)(m0 + row) * HIDDEN + qq * 8);
    }
    uint32_t bDst[8]; const char* bSrc[8]; uint32_t bSz[8];
    #pragma unroll
    for (int i = 0; i < 8; i++) {
        int ch = tid + i * 256;               // 0..2047
        int row = ch >> 3, qq = ch & 7;
        bDst[i] = (uint32_t)(LGA_BYTES + row * (LG_STRIDE * 2) + qq * 16);
        int n = n0 + row;
        bSz[i] = (n < VOCAB) ? 16u : 0u;
        if (n >= VOCAB) n = VOCAB - 1;
        bSrc[i] = (const char*)(g_wth + (size_t)n * HIDDEN + qq * 8);
    }

    // wait until the RNN has published all 128 timesteps of this tile
    {
        const int target = 8 * (tch * 128 + 128);
        if (tid == 0) {
            const int* pp = &g_prog[batch];
            int p;
            while (true) {
                asm volatile("ld.acquire.gpu.global.b32 %0, [%1];"
                             : "=r"(p) : "l"(pp) : "memory");
                if (p >= target) break;
                __nanosleep(256);
            }
        }
        __syncthreads();
    }

    float c[4][8][4];
    #pragma unroll
    for (int mi = 0; mi < 4; mi++)
        #pragma unroll
        for (int ni = 0; ni < 8; ni++)
            #pragma unroll
            for (int j = 0; j < 4; j++) c[mi][ni][j] = 0.f;

    // prologue: stages 0 and 1 (each stage advances 64 halves = 128 bytes)
    #pragma unroll
    for (int st = 0; st < 2; st++) {
        uint32_t base = sb + st * LG_STAGE;
        #pragma unroll
        for (int i = 0; i < 4; i++) CP_A16(base + aDst[i], aSrc[i] + st * 128);
        #pragma unroll
        for (int i = 0; i < 8; i++) CP_A16Z(base + bDst[i], bSrc[i] + st * 128, bSz[i]);
        CP_COMMIT();
    }

    const int aOffBase = (wm * 64 + gr) * LG_STRIDE + 2 * gc;
    const int bOffBase = (wn * 64 + gr) * LG_STRIDE + 2 * gc;

    #pragma unroll 1
    for (int ks = 0; ks < 8; ks++) {
        if (ks < 7) CP_WAIT(1); else CP_WAIT(0);
        __syncthreads();

        if (ks + 2 < 8) {
            const int st = ks + 2;
            uint32_t base = sb + (uint32_t)(st % 3) * LG_STAGE;
            #pragma unroll
            for (int i = 0; i < 4; i++) CP_A16(base + aDst[i], aSrc[i] + st * 128);
            #pragma unroll
            for (int i = 0; i < 8; i++) CP_A16Z(base + bDst[i], bSrc[i] + st * 128, bSz[i]);
            CP_COMMIT();
        }

        const __half* bufA = (const __half*)(smem + (ks % 3) * LG_STAGE);
        const __half* bufB = bufA + LGA_BYTES / 2;

        #pragma unroll
        for (int kk = 0; kk < 64; kk += 16) {
            uint32_t a[4][4];
            #pragma unroll
            for (int mi = 0; mi < 4; mi++) {
                const __half* p = bufA + aOffBase + mi * 16 * LG_STRIDE + kk;
                a[mi][0] = *(const uint32_t*)(p);
                a[mi][1] = *(const uint32_t*)(p + 8 * LG_STRIDE);
                a[mi][2] = *(const uint32_t*)(p + 8);
                a[mi][3] = *(const uint32_t*)(p + 8 * LG_STRIDE + 8);
            }
            uint32_t bfr[8][2];
            #pragma unroll
            for (int ni = 0; ni < 8; ni++) {
                const __half* p = bufB + bOffBase + ni * 8 * LG_STRIDE + kk;
                bfr[ni][0] = *(const uint32_t*)(p);
                bfr[ni][1] = *(const uint32_t*)(p + 8);
            }
            #pragma unroll
            for (int mi = 0; mi < 4; mi++)
                #pragma unroll
                for (int ni = 0; ni < 8; ni++) {
                    asm volatile(
                        "mma.sync.aligned.m16n8k16.row.col.f32.f16.f16.f32 "
                        "{%0,%1,%2,%3}, {%4,%5,%6,%7}, {%8,%9}, {%0,%1,%2,%3};"
                        : "+f"(c[mi][ni][0]), "+f"(c[mi][ni][1]),
                          "+f"(c[mi][ni][2]), "+f"(c[mi][ni][3])
                        : "r"(a[mi][0]), "r"(a[mi][1]), "r"(a[mi][2]), "r"(a[mi][3]),
                          "r"(bfr[ni][0]), "r"(bfr[ni][1]));
                }
        }
    }

    // epilogue: direct gmem stores + bias
    const int mBase = m0 + wm * 64 + gr;
    const int nBase = n0 + wn * 64 + gc * 2;
    #pragma unroll
    for (int ni = 0; ni < 8; ni++) {
        int col = nBase + ni * 8;
        if (col < VOCAB) {
            float2 bias = *(const float2*)(b_out + col);
            #pragma unroll
            for (int mi = 0; mi < 4; mi++) {
                int r0 = mBase + mi * 16;
                float2 v0 = make_float2(c[mi][ni][0] + bias.x, c[mi][ni][1] + bias.y);
                float2 v1 = make_float2(c[mi][ni][2] + bias.x, c[mi][ni][3] + bias.y);
                *(float2*)(out + (size_t)r0 * VOCAB + col)       = v0;
                *(float2*)(out + (size_t)(r0 + 8) * VOCAB + col) = v1;
            }
        }
    }
}

// ---------------------------------------------------------------------------
// Inputs (metadata order):
//  0:x [8,2048] i64/i32  1:hidden [8,512]  2:embedding [16000,256]
//  3:W_ih [512,256]  4:W_hh [512,512]  5:b_ih [512]  6:b_hh [512]
//  7:W_out [16000,512]  8:b_out [16000]
// Output: logits [8,2048,16000] f32 then h_final [8,512] f32.
// ---------------------------------------------------------------------------
extern "C" void kernel_launch(void* const* d_in, const int* in_sizes, int n_in,
                              void* d_out, int out_size)
{
    const long long* x64   = (const long long*)d_in[0];
    const int*       x32   = (const int*)d_in[0];
    const float* hidden    = (const float*)d_in[1];
    const float* embedding = (const float*)d_in[2];
    const float* W_ih      = (const float*)d_in[3];
    const float* W_hh      = (const float*)d_in[4];
    const float* b_ih      = (const float*)d_in[5];
    const float* b_hh      = (const float*)d_in[6];
    const float* W_out     = (const float*)d_in[7];
    const float* b_out     = (const float*)d_in[8];
    float* out = (float*)d_out;

    const int hf_off = out_size - BATCH * HIDDEN;

    static bool attr_set = false;
    if (!attr_set) {
        cudaFuncSetAttribute(logits_mma_kernel,
                             cudaFuncAttributeMaxDynamicSharedMemorySize, LG_SMEM);
        attr_set = true;
    }

    detect_kernel<<<1, 1>>>(x32);

    // combined prep: wconv (2000 blocks) + xproj (512 blocks), overlapped
    prep_kernel<<<2512, 256>>>(W_out, x64, x32, embedding, W_ih, b_ih);

    // RNN: PDL primary (fires launch_dependents after setup)
    rnn_kernel<<<dim3(8, 8), 256>>>(hidden, W_hh, b_hh, out, hf_off);

    // logits GEMM as PDL secondary: begins launching once rnn_kernel's CTAs
    // have executed griddepcontrol.launch_dependents
    {
        cudaLaunchConfig_t cfg = {};
        cfg.gridDim  = dim3(63, 128);
        cfg.blockDim = dim3(256);
        cfg.dynamicSmemBytes = LG_SMEM;
        cfg.stream = 0;
        cudaLaunchAttribute attrs[1];
        attrs[0].id = cudaLaunchAttributeProgrammaticStreamSerialization;
        attrs[0].val.programmaticStreamSerializationAllowed = 1;
        cfg.attrs = attrs;
        cfg.numAttrs = 1;
        cudaLaunchKernelEx(&cfg, logits_mma_kernel, b_out, out);
    }
}